// round 4
// baseline (speedup 1.0000x reference)
#include <cuda_runtime.h>
#include <cstdint>

#define HH 512
#define WW 512
#define CC 19
#define BB 4
#define NP (HH*WW)            // 262144 pixels per plane
#define NPRED (BB*CC)         // 76 pred planes (tgt planes are NPRED..2*NPRED-1)
#define NPL (2*NPRED)         // 152 planes total
#define TILE 32
#define HTILE 34
#define HTILE2 (HTILE*HTILE)  // 1156
#define SMEM_BYTES (CC*HTILE2*4 + HTILE2*4)   // 87856 + 4624 = 92480

// ---------------- device scratch (static allocation: allowed) ----------------
__device__ int            g_labels[NPL*(size_t)NP];   // ~159 MB, touched only at set pixels
__device__ unsigned char  g_mask  [NPL*(size_t)NP];   // ~40 MB
__device__ int            g_setcnt[NPL];
__device__ int            g_mergecnt[NPL];
__device__ int            g_n1;       // #(pred_b & valid)
__device__ int            g_n11;      // #(pred_b & tgt_b & valid)
__device__ int            g_nvalid;   // #valid pixels (B,H,W)
__device__ int            g_is64;     // target dtype flag

// ---------------- init ----------------
__global__ void k_init() {
    int t = threadIdx.x;
    if (t < NPL) { g_setcnt[t] = 0; g_mergecnt[t] = 0; }
    if (t == 0)  { g_n1 = 0; g_n11 = 0; g_nvalid = 0; }
}

// Detect whether target buffer is int64 or int32 (JAX x64-off silently downcasts).
// int64 values are 0..18/255 -> high words all zero. int32 data reinterpreted as
// pairs has nonzero odd-position words with overwhelming probability.
__global__ void k_detect(const int* __restrict__ traw) {
    if (threadIdx.x == 0) {
        int is64 = 1;
        for (int i = 1; i < 8192; i += 2)
            if (traw[i] != 0) { is64 = 0; break; }
        g_is64 = is64;
    }
}

// ---------------- fused softmax + boundary + masks + label init ----------------
__global__ void __launch_bounds__(512)
k_fused(const float* __restrict__ pred, const void* __restrict__ targetv) {
    extern __shared__ float sm[];
    float* S = sm;                        // [CC][34][34] softmax (0 outside image)
    int*   T = (int*)(sm + CC*HTILE2);    // [34][34] target: -2 OOB, -1 ignore, else class

    const int tx = threadIdx.x, ty = threadIdx.y;
    const int tid = ty*32 + tx;                 // 0..511
    const int gx0 = blockIdx.x*TILE, gy0 = blockIdx.y*TILE;
    const int b = blockIdx.z;
    const int is64 = g_is64;
    const long long* t64 = (const long long*)targetv;
    const int*       t32 = (const int*)targetv;

    // --- halo fill: softmax per pixel, all channels ---
    for (int i = tid; i < HTILE2; i += 512) {
        int ly = i / HTILE, lx = i - ly*HTILE;
        int gy = gy0 + ly - 1, gx = gx0 + lx - 1;
        if ((unsigned)gy < HH && (unsigned)gx < WW) {
            const float* base = pred + ((size_t)b*CC)*NP + (size_t)gy*WW + gx;
            float v[CC];
            float mx = -1e30f;
            #pragma unroll
            for (int c = 0; c < CC; c++) { v[c] = base[(size_t)c*NP]; mx = fmaxf(mx, v[c]); }
            float s = 0.f;
            #pragma unroll
            for (int c = 0; c < CC; c++) { v[c] = __expf(v[c] - mx); s += v[c]; }
            float inv = 1.0f / s;
            #pragma unroll
            for (int c = 0; c < CC; c++) S[c*HTILE2 + i] = v[c]*inv;
            size_t toff = (size_t)b*NP + (size_t)gy*WW + gx;
            long long t = is64 ? t64[toff] : (long long)t32[toff];
            T[i] = (t == 255) ? -1 : (int)t;
        } else {
            #pragma unroll
            for (int c = 0; c < CC; c++) S[c*HTILE2 + i] = 0.f;
            T[i] = -2;
        }
    }
    __syncthreads();

    int myN1 = 0, myN11 = 0, myV = 0;

    #pragma unroll
    for (int r = 0; r < 2; r++) {
        const int lyy = ty + r*16;                 // interior tile row 0..31
        const int gy = gy0 + lyy, gx = gx0 + tx;
        const int pix = gy*WW + gx;
        const int li = (lyy+1)*HTILE + (tx+1);
        const int tC = T[li];
        const bool valid = (tC != -1);             // center always in-bounds
        myV += valid;
        const int t0=T[li-HTILE-1], t1=T[li-HTILE], t2=T[li-HTILE+1],
                  t3=T[li-1],                        t4=T[li+1],
                  t5=T[li+HTILE-1], t6=T[li+HTILE], t7=T[li+HTILE+1];
        #pragma unroll
        for (int c = 0; c < CC; c++) {
            const int si = c*HTILE2 + li;
            float sc = S[si];
            float nb = S[si-HTILE-1] + S[si-HTILE] + S[si-HTILE+1]
                     + S[si-1]                      + S[si+1]
                     + S[si+HTILE-1] + S[si+HTILE] + S[si+HTILE+1];
            float lap = 8.0f*sc - nb;
            bool pb = fabsf(lap) > 0.1f;
            int ohc = (tC == c);
            int tnb = (t0==c)+(t1==c)+(t2==c)+(t3==c)+(t4==c)+(t5==c)+(t6==c)+(t7==c);
            bool tb = (8*ohc - tnb) != 0;
            if (valid) { myN1 += pb; myN11 += (pb && tb); }
            bool pm = valid && (sc > 0.5f);
            bool tm = (tC == c);                   // implies valid (ignore stored as -1)
            int pp = b*CC + c;
            int pidx = pp*NP + pix;
            int tidx = (NPRED + pp)*NP + pix;
            g_mask[pidx] = (unsigned char)pm;
            g_mask[tidx] = (unsigned char)tm;
            if (pm) g_labels[pidx] = pidx;
            if (tm) g_labels[tidx] = tidx;
        }
    }

    // warp-reduce the three scalar counters, one atomic per warp
    #pragma unroll
    for (int o = 16; o > 0; o >>= 1) {
        myN1  += __shfl_down_sync(0xffffffffu, myN1,  o);
        myN11 += __shfl_down_sync(0xffffffffu, myN11, o);
        myV   += __shfl_down_sync(0xffffffffu, myV,   o);
    }
    if ((tid & 31) == 0) {
        if (myN1)  atomicAdd(&g_n1,  myN1);
        if (myN11) atomicAdd(&g_n11, myN11);
        if (myV)   atomicAdd(&g_nvalid, myV);
    }
}

// ---------------- union-find (4-connectivity, per-plane) ----------------
__device__ __forceinline__ int findRoot(int x) {
    int p = g_labels[x];
    while (p != x) {
        int gp = g_labels[p];
        if (gp != p) g_labels[x] = gp;   // path halving (parents strictly decrease; race-safe)
        x = p; p = gp;
    }
    return x;
}

// Returns 1 iff this call performed the CAS that merged two distinct trees.
__device__ __forceinline__ int unite(int a, int b) {
    while (true) {
        a = findRoot(a); b = findRoot(b);
        if (a == b) return 0;
        int mx = a > b ? a : b;
        int mn = a > b ? b : a;
        int old = atomicCAS(&g_labels[mx], mx, mn);
        if (old == mx) return 1;         // mx was a root; mn provably in another tree
        a = old; b = mn;
    }
}

__global__ void __launch_bounds__(256) k_merge() {
    const int plane = blockIdx.y;
    const int pix = blockIdx.x*256 + threadIdx.x;
    const int base = plane*NP;
    const int idx = base + pix;
    const bool m = (g_mask[idx] != 0);
    int mrg = 0;
    if (m) {
        int x = pix & (WW-1);
        int y = pix >> 9;
        if (x < WW-1 && g_mask[idx+1])  mrg += unite(idx, idx+1);
        if (y < HH-1 && g_mask[idx+WW]) mrg += unite(idx, idx+WW);
    }
    unsigned bs = __ballot_sync(0xffffffffu, m);
    #pragma unroll
    for (int o = 16; o > 0; o >>= 1) mrg += __shfl_down_sync(0xffffffffu, mrg, o);
    if ((threadIdx.x & 31) == 0) {
        int sc = __popc(bs);
        if (sc)  atomicAdd(&g_setcnt[plane], sc);
        if (mrg) atomicAdd(&g_mergecnt[plane], mrg);
    }
}

// ---------------- final combine ----------------
__global__ void k_final(float* __restrict__ out) {
    __shared__ float red[128];
    int t = threadIdx.x;
    float conn = 0.f;
    if (t < NPRED) {
        int cp = g_setcnt[t]         - g_mergecnt[t];           // pred components
        int ct = g_setcnt[NPRED + t] - g_mergecnt[NPRED + t];   // tgt components
        if (g_setcnt[NPRED + t] > 0) conn = fabsf((float)(cp - ct));
    }
    red[t] = conn;
    __syncthreads();
    for (int o = 64; o > 0; o >>= 1) { if (t < o) red[t] += red[t + o]; __syncthreads(); }
    if (t == 0) {
        const double LN2 = 0.6931471805599453;
        const double S1  = 0.3132616875182228;   // log1p(exp(-1))
        double n1 = (double)g_n1, n11 = (double)g_n11, nv = (double)g_nvalid;
        double Ntot = (double)BB*CC*HH*WW;
        // per-pixel BCE: x=0 -> ln2 ; x=1,y=0 -> 1+S1 ; x=1,y=1 -> S1
        double bsum = (Ntot - n1)*LN2 + n1*(1.0 + S1) - n11;
        double bl = bsum / (nv + 1e-8);
        double cl = (double)red[0] / ((double)(BB*CC) + 1e-8);
        out[0] = (float)(bl + 0.1*cl);
    }
}

// ---------------- launch ----------------
extern "C" void kernel_launch(void* const* d_in, const int* in_sizes, int n_in,
                              void* d_out, int out_size) {
    // Robust input selection: pred is the large float buffer (B*C*H*W elems).
    int pi = 0, ti = 1;
    if (n_in >= 2 && in_sizes[1] == BB*CC*NP && in_sizes[0] != BB*CC*NP) { pi = 1; ti = 0; }
    const float* pred = (const float*)d_in[pi];
    const void*  targ = d_in[ti];
    float* out = (float*)d_out;

    cudaFuncSetAttribute(k_fused, cudaFuncAttributeMaxDynamicSharedMemorySize, SMEM_BYTES);

    k_init<<<1, 256>>>();
    k_detect<<<1, 32>>>((const int*)targ);
    dim3 g1(WW/TILE, HH/TILE, BB), b1(32, 16);
    k_fused<<<g1, b1, SMEM_BYTES>>>(pred, targ);
    k_merge<<<dim3(NP/256, NPL), 256>>>();
    k_final<<<1, 128>>>(out);
}

// round 6
// speedup vs baseline: 3.3405x; 3.3405x over previous
#include <cuda_runtime.h>
#include <cstdint>

#define HH 512
#define WW 512
#define CC 19
#define BB 4
#define NP (HH*WW)            // 262144 pixels per plane
#define NPRED (BB*CC)         // 76 pred planes (tgt planes are NPRED..2*NPRED-1)
#define NPL (2*NPRED)         // 152 planes total
#define TILE 32
#define HTILE 34
#define HTILE2 (HTILE*HTILE)  // 1156
// smem: S[19][34][34] floats + T[34][34] ints + 38 counters
#define SMEM_BYTES (CC*HTILE2*4 + HTILE2*4 + 40*4)

// ---------------- device scratch (static allocation: allowed) ----------------
__device__ int            g_labels[NPL*(size_t)NP];   // touched only at adjacency endpoints
__device__ unsigned int   g_pm[BB*(size_t)NP];        // packed pred masks, 19 bits/pixel (4 MB)
__device__ int            g_setcnt[NPL];
__device__ int            g_mergecnt[NPL];
__device__ int            g_n1;       // #(pred_b & valid)
__device__ int            g_n11;      // #(pred_b & tgt_b & valid)
__device__ int            g_nvalid;   // #valid pixels (B,H,W)
__device__ int            g_is64;     // target dtype flag

// ---------------- init ----------------
__global__ void k_init() {
    int t = threadIdx.x;
    if (t < NPL) { g_setcnt[t] = 0; g_mergecnt[t] = 0; }
    if (t == 0)  { g_n1 = 0; g_n11 = 0; g_nvalid = 0; }
}

// Detect whether target buffer is int64 or int32 (JAX x64-off silently downcasts).
__global__ void k_detect(const int* __restrict__ traw) {
    if (threadIdx.x == 0) {
        int is64 = 1;
        for (int i = 1; i < 8192; i += 2)
            if (traw[i] != 0) { is64 = 0; break; }
        g_is64 = is64;
    }
}

__device__ __forceinline__ int ldT(const void* t, int is64, size_t i) {
    long long v = is64 ? ((const long long*)t)[i] : (long long)((const int*)t)[i];
    return (v == 255) ? -1 : (int)v;    // -1 = ignore
}

// ---------------- fused softmax + boundary + packed masks + sparse label init ----------------
__global__ void __launch_bounds__(512)
k_fused(const float* __restrict__ pred, const void* __restrict__ targetv) {
    extern __shared__ float sm[];
    float* S    = sm;                         // [CC][34][34] softmax (0 outside image)
    int*   T    = (int*)(sm + CC*HTILE2);     // [34][34]: -2 OOB, -1 ignore, else class
    int*   scnt = (int*)(sm + CC*HTILE2 + HTILE2);  // [38] per-plane set counts

    const int tx = threadIdx.x, ty = threadIdx.y;
    const int tid = ty*32 + tx;               // 0..511
    const int gx0 = blockIdx.x*TILE, gy0 = blockIdx.y*TILE;
    const int b = blockIdx.z;
    const int is64 = g_is64;

    if (tid < 38) scnt[tid] = 0;

    // --- halo fill: softmax per pixel, all channels ---
    for (int i = tid; i < HTILE2; i += 512) {
        int ly = i / HTILE, lx = i - ly*HTILE;
        int gy = gy0 + ly - 1, gx = gx0 + lx - 1;
        if ((unsigned)gy < HH && (unsigned)gx < WW) {
            const float* base = pred + ((size_t)b*CC)*NP + (size_t)gy*WW + gx;
            float v[CC];
            float mx = -1e30f;
            #pragma unroll
            for (int c = 0; c < CC; c++) { v[c] = base[(size_t)c*NP]; mx = fmaxf(mx, v[c]); }
            float s = 0.f;
            #pragma unroll
            for (int c = 0; c < CC; c++) { v[c] = __expf(v[c] - mx); s += v[c]; }
            float inv = 1.0f / s;
            #pragma unroll
            for (int c = 0; c < CC; c++) S[c*HTILE2 + i] = v[c]*inv;
            T[i] = ldT(targetv, is64, (size_t)b*NP + (size_t)gy*WW + gx);
        } else {
            #pragma unroll
            for (int c = 0; c < CC; c++) S[c*HTILE2 + i] = 0.f;
            T[i] = -2;
        }
    }
    __syncthreads();

    int myN1 = 0, myN11 = 0, myV = 0;

    #pragma unroll
    for (int r = 0; r < 2; r++) {
        const int lyy = ty + r*16;                 // interior tile row 0..31
        const int gy = gy0 + lyy, gx = gx0 + tx;
        const int pix = gy*WW + gx;
        const int li = (lyy+1)*HTILE + (tx+1);
        const int tC = T[li];
        const bool valid = (tC >= 0);              // center never OOB
        myV += valid;
        const int t0=T[li-HTILE-1], t1=T[li-HTILE], t2=T[li-HTILE+1],
                  t3=T[li-1],       tE=T[li+1],
                  t5=T[li+HTILE-1], tS=T[li+HTILE], t7=T[li+HTILE+1];
        const bool validE = (tE >= 0), validS = (tS >= 0);
        unsigned pmbits = 0u;
        #pragma unroll
        for (int c = 0; c < CC; c++) {
            const int si = c*HTILE2 + li;
            float sc = S[si];
            float scE = S[si+1], scS = S[si+HTILE];
            float nb = S[si-HTILE-1] + S[si-HTILE] + S[si-HTILE+1]
                     + S[si-1]                      + scE
                     + S[si+HTILE-1] + scS          + S[si+HTILE+1];
            float lap = 8.0f*sc - nb;
            bool pb = fabsf(lap) > 0.1f;
            int ohc = (tC == c);
            int tnb = (t0==c)+(t1==c)+(t2==c)+(t3==c)+(tE==c)+(t5==c)+(tS==c)+(t7==c);
            bool tb = (8*ohc - tnb) != 0;
            if (valid) { myN1 += pb; myN11 += (pb && tb); }

            bool pm  = valid  && (sc  > 0.5f);
            bool pmE = validE && (scE > 0.5f);
            bool pmS = validS && (scS > 0.5f);
            bool tm  = (tC == c);                  // -1/-2 never match
            bool tmE = (tE == c);
            bool tmS = (tS == c);
            pmbits |= ((unsigned)pm) << c;

            int pp = b*CC + c;
            int pidx = pp*NP + pix;
            int tidx = (NPRED + pp)*NP + pix;
            // sparse label init: only adjacency endpoints ever enter unite()
            bool eE = pm && pmE, eS = pm && pmS;
            if (eE | eS) g_labels[pidx] = pidx;
            if (eE)      g_labels[pidx+1]  = pidx+1;
            if (eS)      g_labels[pidx+WW] = pidx+WW;
            bool fE = tm && tmE, fS = tm && tmS;
            if (fE | fS) g_labels[tidx] = tidx;
            if (fE)      g_labels[tidx+1]  = tidx+1;
            if (fS)      g_labels[tidx+WW] = tidx+WW;

            // per-plane set counts via warp ballot (one smem atomic per warp per plane)
            unsigned bp = __ballot_sync(0xffffffffu, pm);
            unsigned bt = __ballot_sync(0xffffffffu, tm);
            if (tx == 0) {
                if (bp) atomicAdd(&scnt[c],      __popc(bp));
                if (bt) atomicAdd(&scnt[19 + c], __popc(bt));
            }
        }
        g_pm[(size_t)b*NP + pix] = pmbits;
    }

    // warp-reduce the three scalar counters, one atomic per warp
    #pragma unroll
    for (int o = 16; o > 0; o >>= 1) {
        myN1  += __shfl_down_sync(0xffffffffu, myN1,  o);
        myN11 += __shfl_down_sync(0xffffffffu, myN11, o);
        myV   += __shfl_down_sync(0xffffffffu, myV,   o);
    }
    if (tx == 0) {
        if (myN1)  atomicAdd(&g_n1,  myN1);
        if (myN11) atomicAdd(&g_n11, myN11);
        if (myV)   atomicAdd(&g_nvalid, myV);
    }
    __syncthreads();
    if (tid < 19) {
        int v0 = scnt[tid], v1 = scnt[19 + tid];
        if (v0) atomicAdd(&g_setcnt[b*CC + tid],         v0);
        if (v1) atomicAdd(&g_setcnt[NPRED + b*CC + tid], v1);
    }
}

// ---------------- union-find (4-connectivity, per-plane) ----------------
__device__ __forceinline__ int findRoot(int x) {
    int p = g_labels[x];
    while (p != x) {
        int gp = g_labels[p];
        if (gp != p) g_labels[x] = gp;   // path halving (parents strictly decrease; race-safe)
        x = p; p = gp;
    }
    return x;
}

// Returns 1 iff this call performed the CAS that merged two distinct trees.
__device__ __forceinline__ int unite(int a, int b) {
    while (true) {
        a = findRoot(a); b = findRoot(b);
        if (a == b) return 0;
        int mx = a > b ? a : b;
        int mn = a > b ? b : a;
        int old = atomicCAS(&g_labels[mx], mx, mn);
        if (old == mx) return 1;
        a = old; b = mn;
    }
}

// ---------------- edge detection + union (bitwise over 19 channels) ----------------
__global__ void __launch_bounds__(256) k_unite(const void* __restrict__ targetv) {
    const int b = blockIdx.y;
    const int quad = blockIdx.x*256 + threadIdx.x;   // 0..65535
    const int pix  = quad*4;
    const int x = pix & (WW-1), y = pix >> 9;
    const int is64 = g_is64;
    const unsigned* pmp = g_pm + (size_t)b*NP;

    uint4 q = *(const uint4*)(pmp + pix);
    unsigned pm[5] = {q.x, q.y, q.z, q.w, 0u};
    const bool hasE4 = (x + 4 < WW);
    if (hasE4) pm[4] = pmp[pix + 4];
    const bool hasS = (y + 1 < HH);
    unsigned pmb[4] = {0u,0u,0u,0u};
    if (hasS) {
        uint4 qb = *(const uint4*)(pmp + pix + WW);
        pmb[0]=qb.x; pmb[1]=qb.y; pmb[2]=qb.z; pmb[3]=qb.w;
    }

    const size_t tb = (size_t)b*NP + pix;
    int tc[5], tcb[4];
    #pragma unroll
    for (int e = 0; e < 4; e++) tc[e] = ldT(targetv, is64, tb + e);
    tc[4] = hasE4 ? ldT(targetv, is64, tb + 4) : -9;
    #pragma unroll
    for (int e = 0; e < 4; e++) tcb[e] = hasS ? ldT(targetv, is64, tb + WW + e) : -9;

    const int pbase = b*CC;
    #pragma unroll
    for (int e = 0; e < 4; e++) {
        unsigned aE = pm[e] & pm[e+1];
        while (aE) {
            int c = __ffs(aE) - 1; aE &= aE - 1;
            int pl = pbase + c, base = pl*NP;
            if (unite(base + pix + e, base + pix + e + 1)) atomicAdd(&g_mergecnt[pl], 1);
        }
        unsigned aS = pm[e] & pmb[e];
        while (aS) {
            int c = __ffs(aS) - 1; aS &= aS - 1;
            int pl = pbase + c, base = pl*NP;
            if (unite(base + pix + e, base + pix + e + WW)) atomicAdd(&g_mergecnt[pl], 1);
        }
        if (tc[e] >= 0) {
            if (tc[e] == tc[e+1]) {
                int pl = NPRED + pbase + tc[e], base = pl*NP;
                if (unite(base + pix + e, base + pix + e + 1)) atomicAdd(&g_mergecnt[pl], 1);
            }
            if (tc[e] == tcb[e]) {
                int pl = NPRED + pbase + tc[e], base = pl*NP;
                if (unite(base + pix + e, base + pix + e + WW)) atomicAdd(&g_mergecnt[pl], 1);
            }
        }
    }
}

// ---------------- final combine ----------------
__global__ void k_final(float* __restrict__ out) {
    __shared__ float red[128];
    int t = threadIdx.x;
    float conn = 0.f;
    if (t < NPRED) {
        int cp = g_setcnt[t]         - g_mergecnt[t];           // pred components
        int ct = g_setcnt[NPRED + t] - g_mergecnt[NPRED + t];   // tgt components
        if (g_setcnt[NPRED + t] > 0) conn = fabsf((float)(cp - ct));
    }
    red[t] = conn;
    __syncthreads();
    for (int o = 64; o > 0; o >>= 1) { if (t < o) red[t] += red[t + o]; __syncthreads(); }
    if (t == 0) {
        const double LN2 = 0.6931471805599453;
        const double S1  = 0.3132616875182228;   // log1p(exp(-1))
        double n1 = (double)g_n1, n11 = (double)g_n11, nv = (double)g_nvalid;
        double Ntot = (double)BB*CC*HH*WW;
        // per-pixel BCE: x=0 -> ln2 ; x=1,y=0 -> 1+S1 ; x=1,y=1 -> S1
        double bsum = (Ntot - n1)*LN2 + n1*(1.0 + S1) - n11;
        double bl = bsum / (nv + 1e-8);
        double cl = (double)red[0] / ((double)(BB*CC) + 1e-8);
        out[0] = (float)(bl + 0.1*cl);
    }
}

// ---------------- launch ----------------
extern "C" void kernel_launch(void* const* d_in, const int* in_sizes, int n_in,
                              void* d_out, int out_size) {
    // Robust input selection: pred is the large float buffer (B*C*H*W elems).
    int pi = 0, ti = 1;
    if (n_in >= 2 && in_sizes[1] == BB*CC*NP && in_sizes[0] != BB*CC*NP) { pi = 1; ti = 0; }
    const float* pred = (const float*)d_in[pi];
    const void*  targ = d_in[ti];
    float* out = (float*)d_out;

    cudaFuncSetAttribute(k_fused, cudaFuncAttributeMaxDynamicSharedMemorySize, SMEM_BYTES);

    k_init<<<1, 256>>>();
    k_detect<<<1, 32>>>((const int*)targ);
    dim3 g1(WW/TILE, HH/TILE, BB), b1(32, 16);
    k_fused<<<g1, b1, SMEM_BYTES>>>(pred, targ);
    k_unite<<<dim3(NP/(4*256), BB), 256>>>(targ);
    k_final<<<1, 128>>>(out);
}